// round 11
// baseline (speedup 1.0000x reference)
#include <cuda_runtime.h>
#include <math.h>

#define B_ 2
#define L_ 512
#define C_ 256
#define H_ 8
#define D_ 32
#define SCALE_ 0.17677669529663687f   // 1/sqrt(32)

typedef unsigned long long ull;

// ---------------- f32x2 packed-FMA helpers (sm_103a) ------------------------
__device__ __forceinline__ ull pack2(float a, float b) {
    ull r; asm("mov.b64 %0, {%1, %2};" : "=l"(r) : "f"(a), "f"(b)); return r;
}
__device__ __forceinline__ void unpack2(ull v, float& a, float& b) {
    asm("mov.b64 {%0, %1}, %2;" : "=f"(a), "=f"(b) : "l"(v));
}
__device__ __forceinline__ void ffma2(ull& d, ull a, ull b) {
    asm("fma.rn.f32x2 %0, %1, %2, %0;" : "+l"(d) : "l"(a), "l"(b));
}

// ------------------------- scratch (device globals) -------------------------
__device__ float g_q[B_*H_*L_*D_];          // 1 MB  [b][h][l][d]
__device__ float g_k[B_*H_*L_*D_];          // 1 MB
__device__ float g_v[B_*H_*L_*D_];          // 1 MB
__device__ float g_qk[B_*L_*H_*L_];         // 16 MB [b][l][h][m]
__device__ float g_rel[B_*L_*H_*L_];        // 16 MB [b][l][h][m]
__device__ float g_att[B_*L_*C_];           // 1 MB  [b][l][h*32+d]

// ===========================================================================
// K1 GEMM (qkv, round-2 proven): 64x32 tile, 128 thr; scatter g_q/g_k/g_v.
// ===========================================================================
__global__ __launch_bounds__(128) void gemm_kernel(
    const float* __restrict__ A, const float* __restrict__ W)
{
    __shared__ __align__(16) float As[32][68];
    __shared__ __align__(16) float Ws[32][36];
    int tid  = threadIdx.x;
    int row0 = blockIdx.x * 64;
    int col0 = blockIdx.y * 32;
    int tx = tid & 7, ty = tid >> 3;

    ull acc2[2][4];
    #pragma unroll
    for (int i = 0; i < 2; i++)
        #pragma unroll
        for (int j = 0; j < 4; j++) acc2[i][j] = 0ull;

    for (int kc = 0; kc < 256; kc += 32) {
        #pragma unroll
        for (int i = 0; i < 4; i++) {
            int idx = tid + i * 128;
            int r = idx >> 3, c4 = idx & 7;
            float4 av = *(const float4*)&A[(size_t)(row0 + r) * 256 + kc + c4 * 4];
            As[c4*4+0][r] = av.x; As[c4*4+1][r] = av.y;
            As[c4*4+2][r] = av.z; As[c4*4+3][r] = av.w;
        }
        #pragma unroll
        for (int i = 0; i < 2; i++) {
            int idx = tid + i * 128;
            int r = idx >> 3, c4 = idx & 7;
            float4 wv = *(const float4*)&W[(size_t)(col0 + r) * 256 + kc + c4 * 4];
            Ws[c4*4+0][r] = wv.x; Ws[c4*4+1][r] = wv.y;
            Ws[c4*4+2][r] = wv.z; Ws[c4*4+3][r] = wv.w;
        }
        __syncthreads();
        #pragma unroll
        for (int kk = 0; kk < 32; kk++) {
            ulonglong2 a2 = *(const ulonglong2*)&As[kk][ty * 4];
            float4 b4 = *(const float4*)&Ws[kk][tx * 4];
            ull bd[4] = { pack2(b4.x, b4.x), pack2(b4.y, b4.y),
                          pack2(b4.z, b4.z), pack2(b4.w, b4.w) };
            #pragma unroll
            for (int j = 0; j < 4; j++) {
                ffma2(acc2[0][j], a2.x, bd[j]);
                ffma2(acc2[1][j], a2.y, bd[j]);
            }
        }
        __syncthreads();
    }

    #pragma unroll
    for (int i2 = 0; i2 < 2; i2++) {
        #pragma unroll
        for (int j = 0; j < 4; j++) {
            float v0, v1;
            unpack2(acc2[i2][j], v0, v1);
            int n = col0 + tx * 4 + j;
            #pragma unroll
            for (int half = 0; half < 2; half++) {
                int m  = row0 + ty * 4 + i2 * 2 + half;
                float val = half ? v1 : v0;
                int bb = m >> 9, l = m & 511;
                int s = n >> 8, rem = n & 255, h = rem >> 5, d = rem & 31;
                float* dst = (s == 0) ? g_q : (s == 1) ? g_k : g_v;
                dst[(((size_t)bb * H_ + h) * L_ + l) * D_ + d] = val;
            }
        }
    }
}

// ===========================================================================
// K5 proj GEMM: 32x32 tile, 256 thr, grid (32,8)=256 blocks. A = g_att.
// ===========================================================================
__global__ __launch_bounds__(256) void gemm_proj(
    const float* __restrict__ W, const float* __restrict__ bias,
    float* __restrict__ out)
{
    __shared__ __align__(16) float As[32][34];
    __shared__ __align__(16) float Ws[32][34];
    int tid  = threadIdx.x;
    int row0 = blockIdx.x * 32;
    int col0 = blockIdx.y * 32;
    int tx = tid & 15, ty = tid >> 4;            // n-pair, m-pair

    ull acc0 = 0ull, acc1 = 0ull;

    for (int kc = 0; kc < 256; kc += 32) {
        {
            int r = tid >> 3, c4 = tid & 7;
            float4 av = *(const float4*)&g_att[(size_t)(row0 + r) * 256 + kc + c4 * 4];
            As[c4*4+0][r] = av.x; As[c4*4+1][r] = av.y;
            As[c4*4+2][r] = av.z; As[c4*4+3][r] = av.w;
            float4 wv = *(const float4*)&W[(size_t)(col0 + r) * 256 + kc + c4 * 4];
            Ws[c4*4+0][r] = wv.x; Ws[c4*4+1][r] = wv.y;
            Ws[c4*4+2][r] = wv.z; Ws[c4*4+3][r] = wv.w;
        }
        __syncthreads();
        #pragma unroll
        for (int kk = 0; kk < 32; kk++) {
            ull a2 = *(const ull*)&As[kk][ty * 2];
            float2 wv = *(const float2*)&Ws[kk][tx * 2];
            ffma2(acc0, a2, pack2(wv.x, wv.x));
            ffma2(acc1, a2, pack2(wv.y, wv.y));
        }
        __syncthreads();
    }

    float v0, v1;
    int m0 = row0 + ty * 2, n0 = col0 + tx * 2;
    float b0 = bias[n0], b1 = bias[n0 + 1];
    unpack2(acc0, v0, v1);
    out[(size_t)m0 * 256 + n0]       = v0 + b0;
    out[(size_t)(m0+1) * 256 + n0]   = v1 + b0;
    unpack2(acc1, v0, v1);
    out[(size_t)m0 * 256 + n0+1]     = v0 + b1;
    out[(size_t)(m0+1) * 256 + n0+1] = v1 + b1;
}

// ===========================================================================
// qk (round-6 proven): block=(lt32, bh, mhalf); writes g_qk[b,l,h,m].
// ===========================================================================
__global__ __launch_bounds__(256) void qk_kernel()
{
    __shared__ __align__(16) float ks[256 * 36];
    __shared__ __align__(16) float qs[32 * 32];
    int tid = threadIdx.x;
    int bh = blockIdx.y, lt = blockIdx.x, mh = blockIdx.z;
    int b = bh >> 3, h = bh & 7;

    const float* kb = g_k + (size_t)bh * (512 * 32) + (size_t)mh * 256 * 32;
    const float* qb = g_q + (size_t)bh * (512 * 32) + (size_t)lt * 32 * 32;

    #pragma unroll
    for (int i = 0; i < 8; i++) {
        int idx = tid + i * 256;
        int r = idx >> 3, c4 = idx & 7;
        *(float4*)&ks[r * 36 + c4 * 4] = *(const float4*)&kb[(size_t)idx * 4];
    }
    { int r = tid >> 3, c4 = tid & 7;
      *(float4*)&qs[r * 32 + c4 * 4] = *(const float4*)&qb[(size_t)tid * 4]; }
    __syncthreads();

    int l = tid >> 3, mg = tid & 7;
    ull q2[16];
    #pragma unroll
    for (int j = 0; j < 8; j++) {
        ulonglong2 t = *(const ulonglong2*)&qs[l * 32 + j * 4];
        q2[2*j] = t.x; q2[2*j+1] = t.y;
    }
    float* outp = g_qk + (((size_t)b * 512 + lt * 32 + l) * 8 + h) * 512 + mh * 256;
    #pragma unroll 4
    for (int i = 0; i < 32; i++) {
        int m = mg + i * 8;
        ull sa = 0ull, sb = 0ull;
        #pragma unroll
        for (int j = 0; j < 8; j++) {
            ulonglong2 kv = *(const ulonglong2*)&ks[m * 36 + j * 4];
            ffma2(sa, q2[2*j], kv.x);
            ffma2(sb, q2[2*j+1], kv.y);
        }
        float a0, a1, b0, b1;
        unpack2(sa, a0, a1); unpack2(sb, b0, b1);
        outp[m] = (a0 + a1) + (b0 + b1);
    }
}

// ===========================================================================
// relcompute v3 (FIXED epilogue): 16-c chunks (tile 256x20) for 5 blocks/SM.
// ra[h] holds (even-c, odd-c) partials per h; acc[h] = lo + hi.
// ===========================================================================
__global__ __launch_bounds__(256, 5) void rel_kernel(
    const float* __restrict__ rp, const float* __restrict__ w_rel,
    const float* __restrict__ b_rel, const float* __restrict__ ln_g,
    const float* __restrict__ ln_b)
{
    __shared__ __align__(16) float tile[256 * 20];   // 20 KB
    __shared__ __align__(16) float wp[2048];         // (c-pair, h-pair) weights
    __shared__ float par[24];
    int tid = threadIdx.x;

    #pragma unroll
    for (int i = 0; i < 8; i++) {
        int idx = tid + i * 256;
        int e = idx & 3, h2 = (idx >> 2) & 3, c2 = idx >> 4;
        int h = 2 * h2 + (e >> 1), c = 2 * c2 + (e & 1);
        wp[idx] = w_rel[h * 256 + c];
    }
    if (tid < 8) { par[tid] = b_rel[tid]; par[8+tid] = ln_g[tid]; par[16+tid] = ln_b[tid]; }

    ull ra[8];
    #pragma unroll
    for (int h = 0; h < 8; h++) ra[h] = 0ull;

    const float* rowp = rp + (size_t)blockIdx.x * (256 * 256);
    __syncthreads();

    for (int ch = 0; ch < 16; ch++) {
        #pragma unroll
        for (int i = 0; i < 4; i++) {
            int idx = tid + i * 256;
            int rr = idx >> 2, c4 = idx & 3;
            *(float4*)&tile[rr * 20 + c4 * 4] =
                *(const float4*)&rowp[(size_t)rr * 256 + ch * 16 + c4 * 4];
        }
        __syncthreads();
        const float* trow = &tile[tid * 20];
        #pragma unroll
        for (int c4 = 0; c4 < 4; c4++) {
            ulonglong2 r0 = *(const ulonglong2*)&trow[c4 * 4];
            int g2 = ch * 8 + c4 * 2;
            #pragma unroll
            for (int h2 = 0; h2 < 4; h2++) {
                ulonglong2 wA = *(const ulonglong2*)&wp[(g2 * 4 + h2) * 4];
                ulonglong2 wB = *(const ulonglong2*)&wp[((g2 + 1) * 4 + h2) * 4];
                ffma2(ra[2*h2],   r0.x, wA.x); ffma2(ra[2*h2+1], r0.x, wA.y);
                ffma2(ra[2*h2],   r0.y, wB.x); ffma2(ra[2*h2+1], r0.y, wB.y);
            }
        }
        __syncthreads();
    }

    // FIXED: per-h lane reduction over c-parity
    float acc[8];
    #pragma unroll
    for (int h = 0; h < 8; h++) {
        float lo, hi;
        unpack2(ra[h], lo, hi);
        acc[h] = lo + hi;
    }

    float gv[8];
    float mu = 0.f;
    #pragma unroll
    for (int h = 0; h < 8; h++) {
        float xv = acc[h] + par[h];
        gv[h] = 0.5f * xv * (1.f + erff(xv * 0.7071067811865475f));
        mu += gv[h];
    }
    mu *= 0.125f;
    float var = 0.f;
    #pragma unroll
    for (int h = 0; h < 8; h++) { float d = gv[h] - mu; var += d * d; }
    var *= 0.125f;
    float rstd = rsqrtf(var + 1e-5f);

    size_t r = (size_t)blockIdx.x * 256 + tid;
    size_t base = (r >> 9) * 4096 + (r & 511);
    #pragma unroll
    for (int h = 0; h < 8; h++)
        g_rel[base + (size_t)h * 512] = (gv[h] - mu) * rstd * par[8 + h] + par[16 + h];
}

// ===========================================================================
// attn2 v3: fused (qk+rel)->softmax->PV.  PV remapped: thread = (l-pair,
// d-pair, m-half): each v LDS.64 feeds 2 ffma2; smem reduce over m-halves.
// ===========================================================================
#define AT_LG 520
#define ATTN2_SMEM_FLOATS (16 * AT_LG + 128 * 36 + 256 * 4 + 16)

__global__ __launch_bounds__(256) void attn2_kernel()
{
    extern __shared__ __align__(16) float sm2[];
    float* lg    = sm2;                         // [16][520]  33.3 KB
    float* vs    = sm2 + 16 * AT_LG;            // [128][36]  18.4 KB (chunk)
    float* red   = vs + 128 * 36;               // [256][4]   4 KB
    float* inv_s = red + 256 * 4;               // [16]
    int tid = threadIdx.x;
    int lt = blockIdx.x, bh = blockIdx.y;
    int b = bh >> 3, h = bh & 7;

    const float* vb = g_v + (size_t)bh * (512 * 32);

    // logits = (qk + rel) * scale
    size_t base = ((size_t)(b * 512) + lt * 16) * 4096 + (size_t)h * 512;
    #pragma unroll
    for (int j = 0; j < 8; j++) {
        int idx = tid + j * 256;
        int row = idx >> 7, col4 = idx & 127;
        size_t g = base + (size_t)row * 4096 + col4 * 4;
        float4 a = *(const float4*)&g_qk[g];
        float4 c = *(const float4*)&g_rel[g];
        float4 o;
        o.x = (a.x + c.x) * SCALE_; o.y = (a.y + c.y) * SCALE_;
        o.z = (a.z + c.z) * SCALE_; o.w = (a.w + c.w) * SCALE_;
        *(float4*)&lg[row * AT_LG + col4 * 4] = o;
    }
    __syncthreads();

    // softmax: warp w handles rows 2w, 2w+1
    {
        int lane = tid & 31, w = tid >> 5;
        #pragma unroll
        for (int rr = 0; rr < 2; rr++) {
            float* row = &lg[(w * 2 + rr) * AT_LG];
            float vals[16];
            float mx = -1e30f;
            #pragma unroll
            for (int j = 0; j < 16; j++) { vals[j] = row[lane + 32 * j]; mx = fmaxf(mx, vals[j]); }
            #pragma unroll
            for (int o = 16; o > 0; o >>= 1) mx = fmaxf(mx, __shfl_xor_sync(0xffffffff, mx, o));
            float sum = 0.f;
            #pragma unroll
            for (int j = 0; j < 16; j++) {
                float e = __expf(vals[j] - mx);
                row[lane + 32 * j] = e;
                sum += e;
            }
            #pragma unroll
            for (int o = 16; o > 0; o >>= 1) sum += __shfl_xor_sync(0xffffffff, sum, o);
            if (lane == 0) inv_s[w * 2 + rr] = 1.f / sum;
        }
    }
    __syncthreads();

    // PV: thread = (ms = tid>>7, lp = (tid>>4)&7, dp = tid&15)
    int dp = tid & 15, lp = (tid >> 4) & 7, ms = tid >> 7;
    const float* lrow0 = &lg[(lp * 2 + 0) * AT_LG];
    const float* lrow1 = &lg[(lp * 2 + 1) * AT_LG];
    ull acc0 = 0ull, acc1 = 0ull;
    for (int mc = 0; mc < 4; mc++) {
        #pragma unroll
        for (int i = 0; i < 4; i++) {
            int idx = tid + i * 256;
            int r = idx >> 3, c4 = idx & 7;
            *(float4*)&vs[r * 36 + c4 * 4] =
                *(const float4*)&vb[(size_t)(mc * 128 + r) * 32 + c4 * 4];
        }
        __syncthreads();
        int mb = ms * 64;                         // m-half within chunk
        const float* l0 = lrow0 + mc * 128 + mb;
        const float* l1 = lrow1 + mc * 128 + mb;
        #pragma unroll 4
        for (int m4 = 0; m4 < 16; m4++) {
            float4 p0 = *(const float4*)&l0[m4 * 4];
            float4 p1 = *(const float4*)&l1[m4 * 4];
            float a0[4] = {p0.x, p0.y, p0.z, p0.w};
            float a1[4] = {p1.x, p1.y, p1.z, p1.w};
            #pragma unroll
            for (int s = 0; s < 4; s++) {
                ull vv = *(const ull*)&vs[(mb + m4 * 4 + s) * 36 + dp * 2];
                ffma2(acc0, pack2(a0[s], a0[s]), vv);
                ffma2(acc1, pack2(a1[s], a1[s]), vv);
            }
        }
        __syncthreads();
    }

    // reduce over m-halves
    {
        float x0, x1, y0, y1;
        unpack2(acc0, x0, x1);
        unpack2(acc1, y0, y1);
        *(float4*)&red[tid * 4] = make_float4(x0, x1, y0, y1);
    }
    __syncthreads();
    {
        int l = tid >> 4, dpo = tid & 15;         // output combo
        int lpo = l >> 1, io = l & 1;
        int s0 = lpo * 16 + dpo;                  // ms = 0 source
        int s1 = 128 + s0;                        // ms = 1 source
        float2 v0 = *(const float2*)&red[s0 * 4 + io * 2];
        float2 v1 = *(const float2*)&red[s1 * 4 + io * 2];
        float inv = inv_s[l];
        float2 o = make_float2((v0.x + v1.x) * inv, (v0.y + v1.y) * inv);
        *(float2*)&g_att[((size_t)(b * 512) + lt * 16 + l) * 256 + h * 32 + dpo * 2] = o;
    }
}

// ===========================================================================
extern "C" void kernel_launch(void* const* d_in, const int* in_sizes, int n_in,
                              void* d_out, int out_size)
{
    const float* x      = (const float*)d_in[0];
    const float* rp     = (const float*)d_in[1];
    const float* w_qkv  = (const float*)d_in[2];
    const float* w_rel  = (const float*)d_in[3];
    const float* b_rel  = (const float*)d_in[4];
    const float* ln_g   = (const float*)d_in[5];
    const float* ln_b   = (const float*)d_in[6];
    const float* w_proj = (const float*)d_in[7];
    const float* b_proj = (const float*)d_in[8];
    float* out = (float*)d_out;

    static bool s_init = false;
    static cudaStream_t s_sB;
    static cudaEvent_t s_evF, s_evJ;
    if (!s_init) {
        cudaStreamCreateWithFlags(&s_sB, cudaStreamNonBlocking);
        cudaEventCreateWithFlags(&s_evF, cudaEventDisableTiming);
        cudaEventCreateWithFlags(&s_evJ, cudaEventDisableTiming);
        cudaFuncSetAttribute(attn2_kernel, cudaFuncAttributeMaxDynamicSharedMemorySize,
                             ATTN2_SMEM_FLOATS * (int)sizeof(float));
        s_init = true;
    }

    // fork: side stream runs qkv-gemm + qk while main stream runs relcompute
    cudaEventRecord(s_evF, 0);
    cudaStreamWaitEvent(s_sB, s_evF, 0);

    gemm_kernel<<<dim3(16, 24), 128, 0, s_sB>>>(x, w_qkv);
    qk_kernel<<<dim3(16, 16, 2), 256, 0, s_sB>>>();

    rel_kernel<<<2048, 256>>>(rp, w_rel, b_rel, ln_g, ln_b);   // main stream

    // join
    cudaEventRecord(s_evJ, s_sB);
    cudaStreamWaitEvent(0, s_evJ, 0);

    attn2_kernel<<<dim3(32, 16), 256, ATTN2_SMEM_FLOATS * (int)sizeof(float)>>>();
    gemm_proj<<<dim3(32, 8), 256>>>(w_proj, b_proj, out);
}

// round 12
// speedup vs baseline: 1.0454x; 1.0454x over previous
#include <cuda_runtime.h>
#include <math.h>

#define B_ 2
#define L_ 512
#define C_ 256
#define H_ 8
#define D_ 32
#define SCALE_ 0.17677669529663687f   // 1/sqrt(32)

typedef unsigned long long ull;

// ---------------- f32x2 packed-FMA helpers (sm_103a) ------------------------
__device__ __forceinline__ ull pack2(float a, float b) {
    ull r; asm("mov.b64 %0, {%1, %2};" : "=l"(r) : "f"(a), "f"(b)); return r;
}
__device__ __forceinline__ void unpack2(ull v, float& a, float& b) {
    asm("mov.b64 {%0, %1}, %2;" : "=f"(a), "=f"(b) : "l"(v));
}
__device__ __forceinline__ void ffma2(ull& d, ull a, ull b) {
    asm("fma.rn.f32x2 %0, %1, %2, %0;" : "+l"(d) : "l"(a), "l"(b));
}

// ------------------------- scratch (device globals) -------------------------
__device__ float g_q[B_*H_*L_*D_];          // 1 MB  [b][h][l][d]
__device__ float g_k[B_*H_*L_*D_];          // 1 MB
__device__ float g_v[B_*H_*L_*D_];          // 1 MB
__device__ float g_qk[B_*L_*H_*L_];         // 16 MB [b][l][h][m]
__device__ float g_rel[B_*L_*H_*L_];        // 16 MB [b][l][h][m]
__device__ float g_att[B_*L_*C_];           // 1 MB  [b][l][h*32+d]

// ===========================================================================
// K1 GEMM (qkv, round-2 proven): 64x32 tile, 128 thr; scatter g_q/g_k/g_v.
// ===========================================================================
__global__ __launch_bounds__(128) void gemm_kernel(
    const float* __restrict__ A, const float* __restrict__ W)
{
    __shared__ __align__(16) float As[32][68];
    __shared__ __align__(16) float Ws[32][36];
    int tid  = threadIdx.x;
    int row0 = blockIdx.x * 64;
    int col0 = blockIdx.y * 32;
    int tx = tid & 7, ty = tid >> 3;

    ull acc2[2][4];
    #pragma unroll
    for (int i = 0; i < 2; i++)
        #pragma unroll
        for (int j = 0; j < 4; j++) acc2[i][j] = 0ull;

    for (int kc = 0; kc < 256; kc += 32) {
        #pragma unroll
        for (int i = 0; i < 4; i++) {
            int idx = tid + i * 128;
            int r = idx >> 3, c4 = idx & 7;
            float4 av = *(const float4*)&A[(size_t)(row0 + r) * 256 + kc + c4 * 4];
            As[c4*4+0][r] = av.x; As[c4*4+1][r] = av.y;
            As[c4*4+2][r] = av.z; As[c4*4+3][r] = av.w;
        }
        #pragma unroll
        for (int i = 0; i < 2; i++) {
            int idx = tid + i * 128;
            int r = idx >> 3, c4 = idx & 7;
            float4 wv = *(const float4*)&W[(size_t)(col0 + r) * 256 + kc + c4 * 4];
            Ws[c4*4+0][r] = wv.x; Ws[c4*4+1][r] = wv.y;
            Ws[c4*4+2][r] = wv.z; Ws[c4*4+3][r] = wv.w;
        }
        __syncthreads();
        #pragma unroll
        for (int kk = 0; kk < 32; kk++) {
            ulonglong2 a2 = *(const ulonglong2*)&As[kk][ty * 4];
            float4 b4 = *(const float4*)&Ws[kk][tx * 4];
            ull bd[4] = { pack2(b4.x, b4.x), pack2(b4.y, b4.y),
                          pack2(b4.z, b4.z), pack2(b4.w, b4.w) };
            #pragma unroll
            for (int j = 0; j < 4; j++) {
                ffma2(acc2[0][j], a2.x, bd[j]);
                ffma2(acc2[1][j], a2.y, bd[j]);
            }
        }
        __syncthreads();
    }

    #pragma unroll
    for (int i2 = 0; i2 < 2; i2++) {
        #pragma unroll
        for (int j = 0; j < 4; j++) {
            float v0, v1;
            unpack2(acc2[i2][j], v0, v1);
            int n = col0 + tx * 4 + j;
            #pragma unroll
            for (int half = 0; half < 2; half++) {
                int m  = row0 + ty * 4 + i2 * 2 + half;
                float val = half ? v1 : v0;
                int bb = m >> 9, l = m & 511;
                int s = n >> 8, rem = n & 255, h = rem >> 5, d = rem & 31;
                float* dst = (s == 0) ? g_q : (s == 1) ? g_k : g_v;
                dst[(((size_t)bb * H_ + h) * L_ + l) * D_ + d] = val;
            }
        }
    }
}

// ===========================================================================
// K5 proj GEMM: 32x32 tile, 256 thr, grid (32,8)=256 blocks. A = g_att.
// ===========================================================================
__global__ __launch_bounds__(256) void gemm_proj(
    const float* __restrict__ W, const float* __restrict__ bias,
    float* __restrict__ out)
{
    __shared__ __align__(16) float As[32][34];
    __shared__ __align__(16) float Ws[32][34];
    int tid  = threadIdx.x;
    int row0 = blockIdx.x * 32;
    int col0 = blockIdx.y * 32;
    int tx = tid & 15, ty = tid >> 4;            // n-pair, m-pair

    ull acc0 = 0ull, acc1 = 0ull;

    for (int kc = 0; kc < 256; kc += 32) {
        {
            int r = tid >> 3, c4 = tid & 7;
            float4 av = *(const float4*)&g_att[(size_t)(row0 + r) * 256 + kc + c4 * 4];
            As[c4*4+0][r] = av.x; As[c4*4+1][r] = av.y;
            As[c4*4+2][r] = av.z; As[c4*4+3][r] = av.w;
            float4 wv = *(const float4*)&W[(size_t)(col0 + r) * 256 + kc + c4 * 4];
            Ws[c4*4+0][r] = wv.x; Ws[c4*4+1][r] = wv.y;
            Ws[c4*4+2][r] = wv.z; Ws[c4*4+3][r] = wv.w;
        }
        __syncthreads();
        #pragma unroll
        for (int kk = 0; kk < 32; kk++) {
            ull a2 = *(const ull*)&As[kk][ty * 2];
            float2 wv = *(const float2*)&Ws[kk][tx * 2];
            ffma2(acc0, a2, pack2(wv.x, wv.x));
            ffma2(acc1, a2, pack2(wv.y, wv.y));
        }
        __syncthreads();
    }

    float v0, v1;
    int m0 = row0 + ty * 2, n0 = col0 + tx * 2;
    float b0 = bias[n0], b1 = bias[n0 + 1];
    unpack2(acc0, v0, v1);
    out[(size_t)m0 * 256 + n0]       = v0 + b0;
    out[(size_t)(m0+1) * 256 + n0]   = v1 + b0;
    unpack2(acc1, v0, v1);
    out[(size_t)m0 * 256 + n0+1]     = v0 + b1;
    out[(size_t)(m0+1) * 256 + n0+1] = v1 + b1;
}

// ===========================================================================
// qk (round-6 proven): block=(lt32, bh, mhalf); writes g_qk[b,l,h,m].
// ===========================================================================
__global__ __launch_bounds__(256) void qk_kernel()
{
    __shared__ __align__(16) float ks[256 * 36];
    __shared__ __align__(16) float qs[32 * 32];
    int tid = threadIdx.x;
    int bh = blockIdx.y, lt = blockIdx.x, mh = blockIdx.z;
    int b = bh >> 3, h = bh & 7;

    const float* kb = g_k + (size_t)bh * (512 * 32) + (size_t)mh * 256 * 32;
    const float* qb = g_q + (size_t)bh * (512 * 32) + (size_t)lt * 32 * 32;

    #pragma unroll
    for (int i = 0; i < 8; i++) {
        int idx = tid + i * 256;
        int r = idx >> 3, c4 = idx & 7;
        *(float4*)&ks[r * 36 + c4 * 4] = *(const float4*)&kb[(size_t)idx * 4];
    }
    { int r = tid >> 3, c4 = tid & 7;
      *(float4*)&qs[r * 32 + c4 * 4] = *(const float4*)&qb[(size_t)tid * 4]; }
    __syncthreads();

    int l = tid >> 3, mg = tid & 7;
    ull q2[16];
    #pragma unroll
    for (int j = 0; j < 8; j++) {
        ulonglong2 t = *(const ulonglong2*)&qs[l * 32 + j * 4];
        q2[2*j] = t.x; q2[2*j+1] = t.y;
    }
    float* outp = g_qk + (((size_t)b * 512 + lt * 32 + l) * 8 + h) * 512 + mh * 256;
    #pragma unroll 4
    for (int i = 0; i < 32; i++) {
        int m = mg + i * 8;
        ull sa = 0ull, sb = 0ull;
        #pragma unroll
        for (int j = 0; j < 8; j++) {
            ulonglong2 kv = *(const ulonglong2*)&ks[m * 36 + j * 4];
            ffma2(sa, q2[2*j], kv.x);
            ffma2(sb, q2[2*j+1], kv.y);
        }
        float a0, a1, b0, b1;
        unpack2(sa, a0, a1); unpack2(sb, b0, b1);
        outp[m] = (a0 + a1) + (b0 + b1);
    }
}

// ===========================================================================
// relcompute v4: 2 ROWS PER THREAD — weight broadcasts amortized 2x.
// block = one (b,l) slice (512 m-rows), grid 1024; 16-c chunks, tile 512x20.
// Crossbar model: (32w + 8trow + 8sts)*4 = 192 cyc/warp/chunk -> ~89us chip,
// under the ~96us DRAM floor -> DRAM-bound.
// ===========================================================================
__global__ __launch_bounds__(256) void rel_kernel(
    const float* __restrict__ rp, const float* __restrict__ w_rel,
    const float* __restrict__ b_rel, const float* __restrict__ ln_g,
    const float* __restrict__ ln_b)
{
    __shared__ __align__(16) float tile[512 * 20];   // 40 KB
    __shared__ __align__(16) float wp[2048];         // (c-pair, h-pair) weights
    __shared__ float par[24];
    int tid = threadIdx.x;
    int bid = blockIdx.x;                            // = b*512 + l

    #pragma unroll
    for (int i = 0; i < 8; i++) {
        int idx = tid + i * 256;
        int e = idx & 3, h2 = (idx >> 2) & 3, c2 = idx >> 4;
        int h = 2 * h2 + (e >> 1), c = 2 * c2 + (e & 1);
        wp[idx] = w_rel[h * 256 + c];
    }
    if (tid < 8) { par[tid] = b_rel[tid]; par[8+tid] = ln_g[tid]; par[16+tid] = ln_b[tid]; }

    ull ra0[8], ra1[8];
    #pragma unroll
    for (int h = 0; h < 8; h++) { ra0[h] = 0ull; ra1[h] = 0ull; }

    const float* rpb = rp + (size_t)bid * (512 * 256);
    __syncthreads();

    for (int ch = 0; ch < 16; ch++) {
        #pragma unroll
        for (int i = 0; i < 8; i++) {                 // stage 512 rows x 16 c
            int idx = tid + i * 256;
            int rr = idx >> 2, c4 = idx & 3;
            *(float4*)&tile[rr * 20 + c4 * 4] =
                *(const float4*)&rpb[(size_t)rr * 256 + ch * 16 + c4 * 4];
        }
        __syncthreads();
        const float* t0 = &tile[tid * 20];
        const float* t1 = &tile[(tid + 256) * 20];
        #pragma unroll
        for (int c4 = 0; c4 < 4; c4++) {
            ulonglong2 r0 = *(const ulonglong2*)&t0[c4 * 4];
            ulonglong2 r1 = *(const ulonglong2*)&t1[c4 * 4];
            int g2 = ch * 8 + c4 * 2;
            #pragma unroll
            for (int h2 = 0; h2 < 4; h2++) {
                ulonglong2 wA = *(const ulonglong2*)&wp[(g2 * 4 + h2) * 4];
                ulonglong2 wB = *(const ulonglong2*)&wp[((g2 + 1) * 4 + h2) * 4];
                ffma2(ra0[2*h2],   r0.x, wA.x); ffma2(ra0[2*h2+1], r0.x, wA.y);
                ffma2(ra0[2*h2],   r0.y, wB.x); ffma2(ra0[2*h2+1], r0.y, wB.y);
                ffma2(ra1[2*h2],   r1.x, wA.x); ffma2(ra1[2*h2+1], r1.x, wA.y);
                ffma2(ra1[2*h2],   r1.y, wB.x); ffma2(ra1[2*h2+1], r1.y, wB.y);
            }
        }
        __syncthreads();
    }

    // epilogue for both rows: per-h c-parity reduction, GELU, LN, store
    #pragma unroll
    for (int rr = 0; rr < 2; rr++) {
        ull* ra = rr ? ra1 : ra0;
        float gv[8];
        float mu = 0.f;
        #pragma unroll
        for (int h = 0; h < 8; h++) {
            float lo, hi;
            unpack2(ra[h], lo, hi);
            float xv = lo + hi + par[h];
            gv[h] = 0.5f * xv * (1.f + erff(xv * 0.7071067811865475f));
            mu += gv[h];
        }
        mu *= 0.125f;
        float var = 0.f;
        #pragma unroll
        for (int h = 0; h < 8; h++) { float d = gv[h] - mu; var += d * d; }
        var *= 0.125f;
        float rstd = rsqrtf(var + 1e-5f);

        int m = tid + rr * 256;
        size_t base = (size_t)bid * 4096 + m;
        #pragma unroll
        for (int h = 0; h < 8; h++)
            g_rel[base + (size_t)h * 512] =
                (gv[h] - mu) * rstd * par[8 + h] + par[16 + h];
    }
}

// ===========================================================================
// attn2 v3 (round-11 proven, 26.5us): fused (qk+rel)->softmax->PV.
// ===========================================================================
#define AT_LG 520
#define ATTN2_SMEM_FLOATS (16 * AT_LG + 128 * 36 + 256 * 4 + 16)

__global__ __launch_bounds__(256) void attn2_kernel()
{
    extern __shared__ __align__(16) float sm2[];
    float* lg    = sm2;                         // [16][520]  33.3 KB
    float* vs    = sm2 + 16 * AT_LG;            // [128][36]  18.4 KB (chunk)
    float* red   = vs + 128 * 36;               // [256][4]   4 KB
    float* inv_s = red + 256 * 4;               // [16]
    int tid = threadIdx.x;
    int lt = blockIdx.x, bh = blockIdx.y;
    int b = bh >> 3, h = bh & 7;

    const float* vb = g_v + (size_t)bh * (512 * 32);

    // logits = (qk + rel) * scale
    size_t base = ((size_t)(b * 512) + lt * 16) * 4096 + (size_t)h * 512;
    #pragma unroll
    for (int j = 0; j < 8; j++) {
        int idx = tid + j * 256;
        int row = idx >> 7, col4 = idx & 127;
        size_t g = base + (size_t)row * 4096 + col4 * 4;
        float4 a = *(const float4*)&g_qk[g];
        float4 c = *(const float4*)&g_rel[g];
        float4 o;
        o.x = (a.x + c.x) * SCALE_; o.y = (a.y + c.y) * SCALE_;
        o.z = (a.z + c.z) * SCALE_; o.w = (a.w + c.w) * SCALE_;
        *(float4*)&lg[row * AT_LG + col4 * 4] = o;
    }
    __syncthreads();

    // softmax: warp w handles rows 2w, 2w+1
    {
        int lane = tid & 31, w = tid >> 5;
        #pragma unroll
        for (int rr = 0; rr < 2; rr++) {
            float* row = &lg[(w * 2 + rr) * AT_LG];
            float vals[16];
            float mx = -1e30f;
            #pragma unroll
            for (int j = 0; j < 16; j++) { vals[j] = row[lane + 32 * j]; mx = fmaxf(mx, vals[j]); }
            #pragma unroll
            for (int o = 16; o > 0; o >>= 1) mx = fmaxf(mx, __shfl_xor_sync(0xffffffff, mx, o));
            float sum = 0.f;
            #pragma unroll
            for (int j = 0; j < 16; j++) {
                float e = __expf(vals[j] - mx);
                row[lane + 32 * j] = e;
                sum += e;
            }
            #pragma unroll
            for (int o = 16; o > 0; o >>= 1) sum += __shfl_xor_sync(0xffffffff, sum, o);
            if (lane == 0) inv_s[w * 2 + rr] = 1.f / sum;
        }
    }
    __syncthreads();

    // PV: thread = (ms = tid>>7, lp = (tid>>4)&7, dp = tid&15)
    int dp = tid & 15, lp = (tid >> 4) & 7, ms = tid >> 7;
    const float* lrow0 = &lg[(lp * 2 + 0) * AT_LG];
    const float* lrow1 = &lg[(lp * 2 + 1) * AT_LG];
    ull acc0 = 0ull, acc1 = 0ull;
    for (int mc = 0; mc < 4; mc++) {
        #pragma unroll
        for (int i = 0; i < 4; i++) {
            int idx = tid + i * 256;
            int r = idx >> 3, c4 = idx & 7;
            *(float4*)&vs[r * 36 + c4 * 4] =
                *(const float4*)&vb[(size_t)(mc * 128 + r) * 32 + c4 * 4];
        }
        __syncthreads();
        int mb = ms * 64;                         // m-half within chunk
        const float* l0 = lrow0 + mc * 128 + mb;
        const float* l1 = lrow1 + mc * 128 + mb;
        #pragma unroll 4
        for (int m4 = 0; m4 < 16; m4++) {
            float4 p0 = *(const float4*)&l0[m4 * 4];
            float4 p1 = *(const float4*)&l1[m4 * 4];
            float a0[4] = {p0.x, p0.y, p0.z, p0.w};
            float a1[4] = {p1.x, p1.y, p1.z, p1.w};
            #pragma unroll
            for (int s = 0; s < 4; s++) {
                ull vv = *(const ull*)&vs[(mb + m4 * 4 + s) * 36 + dp * 2];
                ffma2(acc0, pack2(a0[s], a0[s]), vv);
                ffma2(acc1, pack2(a1[s], a1[s]), vv);
            }
        }
        __syncthreads();
    }

    // reduce over m-halves
    {
        float x0, x1, y0, y1;
        unpack2(acc0, x0, x1);
        unpack2(acc1, y0, y1);
        *(float4*)&red[tid * 4] = make_float4(x0, x1, y0, y1);
    }
    __syncthreads();
    {
        int l = tid >> 4, dpo = tid & 15;         // output combo
        int lpo = l >> 1, io = l & 1;
        int s0 = lpo * 16 + dpo;                  // ms = 0 source
        int s1 = 128 + s0;                        // ms = 1 source
        float2 v0 = *(const float2*)&red[s0 * 4 + io * 2];
        float2 v1 = *(const float2*)&red[s1 * 4 + io * 2];
        float inv = inv_s[l];
        float2 o = make_float2((v0.x + v1.x) * inv, (v0.y + v1.y) * inv);
        *(float2*)&g_att[((size_t)(b * 512) + lt * 16 + l) * 256 + h * 32 + dpo * 2] = o;
    }
}

// ===========================================================================
extern "C" void kernel_launch(void* const* d_in, const int* in_sizes, int n_in,
                              void* d_out, int out_size)
{
    const float* x      = (const float*)d_in[0];
    const float* rp     = (const float*)d_in[1];
    const float* w_qkv  = (const float*)d_in[2];
    const float* w_rel  = (const float*)d_in[3];
    const float* b_rel  = (const float*)d_in[4];
    const float* ln_g   = (const float*)d_in[5];
    const float* ln_b   = (const float*)d_in[6];
    const float* w_proj = (const float*)d_in[7];
    const float* b_proj = (const float*)d_in[8];
    float* out = (float*)d_out;

    static bool s_init = false;
    static cudaStream_t s_sB;
    static cudaEvent_t s_evF, s_evJ;
    if (!s_init) {
        cudaStreamCreateWithFlags(&s_sB, cudaStreamNonBlocking);
        cudaEventCreateWithFlags(&s_evF, cudaEventDisableTiming);
        cudaEventCreateWithFlags(&s_evJ, cudaEventDisableTiming);
        cudaFuncSetAttribute(attn2_kernel, cudaFuncAttributeMaxDynamicSharedMemorySize,
                             ATTN2_SMEM_FLOATS * (int)sizeof(float));
        s_init = true;
    }

    // fork: side stream runs qkv-gemm + qk while main stream runs relcompute
    cudaEventRecord(s_evF, 0);
    cudaStreamWaitEvent(s_sB, s_evF, 0);

    gemm_kernel<<<dim3(16, 24), 128, 0, s_sB>>>(x, w_qkv);
    qk_kernel<<<dim3(16, 16, 2), 256, 0, s_sB>>>();

    rel_kernel<<<1024, 256>>>(rp, w_rel, b_rel, ln_g, ln_b);   // main stream

    // join
    cudaEventRecord(s_evJ, s_sB);
    cudaStreamWaitEvent(0, s_evJ, 0);

    attn2_kernel<<<dim3(32, 16), 256, ATTN2_SMEM_FLOATS * (int)sizeof(float)>>>();
    gemm_proj<<<dim3(32, 8), 256>>>(w_proj, b_proj, out);
}

// round 13
// speedup vs baseline: 1.1636x; 1.1131x over previous
#include <cuda_runtime.h>
#include <math.h>

#define B_ 2
#define L_ 512
#define C_ 256
#define H_ 8
#define D_ 32
#define SCALE_ 0.17677669529663687f   // 1/sqrt(32)

typedef unsigned long long ull;

// ---------------- f32x2 packed-FMA helpers (sm_103a) ------------------------
__device__ __forceinline__ ull pack2(float a, float b) {
    ull r; asm("mov.b64 %0, {%1, %2};" : "=l"(r) : "f"(a), "f"(b)); return r;
}
__device__ __forceinline__ void unpack2(ull v, float& a, float& b) {
    asm("mov.b64 {%0, %1}, %2;" : "=f"(a), "=f"(b) : "l"(v));
}
__device__ __forceinline__ void ffma2(ull& d, ull a, ull b) {
    asm("fma.rn.f32x2 %0, %1, %2, %0;" : "+l"(d) : "l"(a), "l"(b));
}

// ------------------------- scratch (device globals) -------------------------
__device__ float g_q[B_*H_*L_*D_];          // 1 MB  [b][h][l][d]
__device__ float g_k[B_*H_*L_*D_];          // 1 MB
__device__ float g_v[B_*H_*L_*D_];          // 1 MB
__device__ float g_qk[B_*L_*H_*L_];         // 16 MB [b][l][h][m]
__device__ float g_rel[B_*L_*H_*L_];        // 16 MB [b][l][h][m]
__device__ float g_att[B_*L_*C_];           // 1 MB  [b][l][h*32+d]

// ===========================================================================
// K1 GEMM (qkv, round-2 proven): 64x32 tile, 128 thr; scatter g_q/g_k/g_v.
// ===========================================================================
__global__ __launch_bounds__(128) void gemm_kernel(
    const float* __restrict__ A, const float* __restrict__ W)
{
    __shared__ __align__(16) float As[32][68];
    __shared__ __align__(16) float Ws[32][36];
    int tid  = threadIdx.x;
    int row0 = blockIdx.x * 64;
    int col0 = blockIdx.y * 32;
    int tx = tid & 7, ty = tid >> 3;

    ull acc2[2][4];
    #pragma unroll
    for (int i = 0; i < 2; i++)
        #pragma unroll
        for (int j = 0; j < 4; j++) acc2[i][j] = 0ull;

    for (int kc = 0; kc < 256; kc += 32) {
        #pragma unroll
        for (int i = 0; i < 4; i++) {
            int idx = tid + i * 128;
            int r = idx >> 3, c4 = idx & 7;
            float4 av = *(const float4*)&A[(size_t)(row0 + r) * 256 + kc + c4 * 4];
            As[c4*4+0][r] = av.x; As[c4*4+1][r] = av.y;
            As[c4*4+2][r] = av.z; As[c4*4+3][r] = av.w;
        }
        #pragma unroll
        for (int i = 0; i < 2; i++) {
            int idx = tid + i * 128;
            int r = idx >> 3, c4 = idx & 7;
            float4 wv = *(const float4*)&W[(size_t)(col0 + r) * 256 + kc + c4 * 4];
            Ws[c4*4+0][r] = wv.x; Ws[c4*4+1][r] = wv.y;
            Ws[c4*4+2][r] = wv.z; Ws[c4*4+3][r] = wv.w;
        }
        __syncthreads();
        #pragma unroll
        for (int kk = 0; kk < 32; kk++) {
            ulonglong2 a2 = *(const ulonglong2*)&As[kk][ty * 4];
            float4 b4 = *(const float4*)&Ws[kk][tx * 4];
            ull bd[4] = { pack2(b4.x, b4.x), pack2(b4.y, b4.y),
                          pack2(b4.z, b4.z), pack2(b4.w, b4.w) };
            #pragma unroll
            for (int j = 0; j < 4; j++) {
                ffma2(acc2[0][j], a2.x, bd[j]);
                ffma2(acc2[1][j], a2.y, bd[j]);
            }
        }
        __syncthreads();
    }

    #pragma unroll
    for (int i2 = 0; i2 < 2; i2++) {
        #pragma unroll
        for (int j = 0; j < 4; j++) {
            float v0, v1;
            unpack2(acc2[i2][j], v0, v1);
            int n = col0 + tx * 4 + j;
            #pragma unroll
            for (int half = 0; half < 2; half++) {
                int m  = row0 + ty * 4 + i2 * 2 + half;
                float val = half ? v1 : v0;
                int bb = m >> 9, l = m & 511;
                int s = n >> 8, rem = n & 255, h = rem >> 5, d = rem & 31;
                float* dst = (s == 0) ? g_q : (s == 1) ? g_k : g_v;
                dst[(((size_t)bb * H_ + h) * L_ + l) * D_ + d] = val;
            }
        }
    }
}

// ===========================================================================
// K5 proj GEMM: 32x32 tile, 256 thr; row-offset param for half-pipelining.
// ===========================================================================
__global__ __launch_bounds__(256) void gemm_proj(
    const float* __restrict__ W, const float* __restrict__ bias,
    float* __restrict__ out, int rb0)
{
    __shared__ __align__(16) float As[32][34];
    __shared__ __align__(16) float Ws[32][34];
    int tid  = threadIdx.x;
    int row0 = (rb0 + blockIdx.x) * 32;
    int col0 = blockIdx.y * 32;
    int tx = tid & 15, ty = tid >> 4;            // n-pair, m-pair

    ull acc0 = 0ull, acc1 = 0ull;

    for (int kc = 0; kc < 256; kc += 32) {
        {
            int r = tid >> 3, c4 = tid & 7;
            float4 av = *(const float4*)&g_att[(size_t)(row0 + r) * 256 + kc + c4 * 4];
            As[c4*4+0][r] = av.x; As[c4*4+1][r] = av.y;
            As[c4*4+2][r] = av.z; As[c4*4+3][r] = av.w;
            float4 wv = *(const float4*)&W[(size_t)(col0 + r) * 256 + kc + c4 * 4];
            Ws[c4*4+0][r] = wv.x; Ws[c4*4+1][r] = wv.y;
            Ws[c4*4+2][r] = wv.z; Ws[c4*4+3][r] = wv.w;
        }
        __syncthreads();
        #pragma unroll
        for (int kk = 0; kk < 32; kk++) {
            ull a2 = *(const ull*)&As[kk][ty * 2];
            float2 wv = *(const float2*)&Ws[kk][tx * 2];
            ffma2(acc0, a2, pack2(wv.x, wv.x));
            ffma2(acc1, a2, pack2(wv.y, wv.y));
        }
        __syncthreads();
    }

    float v0, v1;
    int m0 = row0 + ty * 2, n0 = col0 + tx * 2;
    float b0 = bias[n0], b1 = bias[n0 + 1];
    unpack2(acc0, v0, v1);
    out[(size_t)m0 * 256 + n0]       = v0 + b0;
    out[(size_t)(m0+1) * 256 + n0]   = v1 + b0;
    unpack2(acc1, v0, v1);
    out[(size_t)m0 * 256 + n0+1]     = v0 + b1;
    out[(size_t)(m0+1) * 256 + n0+1] = v1 + b1;
}

// ===========================================================================
// qk (round-6 proven): block=(lt32, bh, mhalf); writes g_qk[b,l,h,m].
// ===========================================================================
__global__ __launch_bounds__(256) void qk_kernel()
{
    __shared__ __align__(16) float ks[256 * 36];
    __shared__ __align__(16) float qs[32 * 32];
    int tid = threadIdx.x;
    int bh = blockIdx.y, lt = blockIdx.x, mh = blockIdx.z;
    int b = bh >> 3, h = bh & 7;

    const float* kb = g_k + (size_t)bh * (512 * 32) + (size_t)mh * 256 * 32;
    const float* qb = g_q + (size_t)bh * (512 * 32) + (size_t)lt * 32 * 32;

    #pragma unroll
    for (int i = 0; i < 8; i++) {
        int idx = tid + i * 256;
        int r = idx >> 3, c4 = idx & 7;
        *(float4*)&ks[r * 36 + c4 * 4] = *(const float4*)&kb[(size_t)idx * 4];
    }
    { int r = tid >> 3, c4 = tid & 7;
      *(float4*)&qs[r * 32 + c4 * 4] = *(const float4*)&qb[(size_t)tid * 4]; }
    __syncthreads();

    int l = tid >> 3, mg = tid & 7;
    ull q2[16];
    #pragma unroll
    for (int j = 0; j < 8; j++) {
        ulonglong2 t = *(const ulonglong2*)&qs[l * 32 + j * 4];
        q2[2*j] = t.x; q2[2*j+1] = t.y;
    }
    float* outp = g_qk + (((size_t)b * 512 + lt * 32 + l) * 8 + h) * 512 + mh * 256;
    #pragma unroll 4
    for (int i = 0; i < 32; i++) {
        int m = mg + i * 8;
        ull sa = 0ull, sb = 0ull;
        #pragma unroll
        for (int j = 0; j < 8; j++) {
            ulonglong2 kv = *(const ulonglong2*)&ks[m * 36 + j * 4];
            ffma2(sa, q2[2*j], kv.x);
            ffma2(sb, q2[2*j+1], kv.y);
        }
        float a0, a1, b0, b1;
        unpack2(sa, a0, a1); unpack2(sb, b0, b1);
        outp[m] = (a0 + a1) + (b0 + b1);
    }
}

// ===========================================================================
// relcompute (round-8 exact, best-measured; bid offset for half-pipelining):
// 256 rows/block, 1 row/thread, 32c chunks, stride-36 tile, ws[c*8+h].
// ===========================================================================
__global__ __launch_bounds__(256, 4) void rel_kernel(
    const float* __restrict__ rp, const float* __restrict__ w_rel,
    const float* __restrict__ b_rel, const float* __restrict__ ln_g,
    const float* __restrict__ ln_b, int bid0)
{
    __shared__ __align__(16) float tile[256 * 36];
    __shared__ __align__(16) float ws[256 * 8];     // ws[c*8 + h]
    __shared__ float par[24];
    int tid = threadIdx.x;
    int bid = bid0 + blockIdx.x;

    #pragma unroll
    for (int i = 0; i < 8; i++) {
        int idx = tid + i * 256;                     // idx = h*256 + c
        ws[(idx & 255) * 8 + (idx >> 8)] = w_rel[idx];
    }
    if (tid < 8) { par[tid] = b_rel[tid]; par[8+tid] = ln_g[tid]; par[16+tid] = ln_b[tid]; }

    ull acc2[4] = {0ull, 0ull, 0ull, 0ull};         // h pairs
    const float* rowp = rp + (size_t)bid * (256 * 256);
    __syncthreads();

    for (int ch = 0; ch < 8; ch++) {
        #pragma unroll
        for (int i = 0; i < 8; i++) {
            int idx = tid + i * 256;
            int rr = idx >> 3, c4 = idx & 7;
            float4 v = *(const float4*)&rowp[(size_t)rr * 256 + ch * 32 + c4 * 4];
            *(float4*)&tile[rr * 36 + c4 * 4] = v;
        }
        __syncthreads();
        const float* trow = &tile[tid * 36];
        #pragma unroll
        for (int c = 0; c < 32; c += 4) {
            float4 r4 = *(const float4*)&trow[c];
            float rv[4] = {r4.x, r4.y, r4.z, r4.w};
            #pragma unroll
            for (int u = 0; u < 4; u++) {
                ull rd = pack2(rv[u], rv[u]);
                ulonglong2 w01 = *(const ulonglong2*)&ws[(ch * 32 + c + u) * 8];
                ulonglong2 w23 = *(const ulonglong2*)&ws[(ch * 32 + c + u) * 8 + 4];
                ffma2(acc2[0], rd, w01.x);
                ffma2(acc2[1], rd, w01.y);
                ffma2(acc2[2], rd, w23.x);
                ffma2(acc2[3], rd, w23.y);
            }
        }
        __syncthreads();
    }

    float acc[8];
    #pragma unroll
    for (int p = 0; p < 4; p++) unpack2(acc2[p], acc[2*p], acc[2*p+1]);

    float gv[8];
    float mu = 0.f;
    #pragma unroll
    for (int h = 0; h < 8; h++) {
        float xv = acc[h] + par[h];
        gv[h] = 0.5f * xv * (1.f + erff(xv * 0.7071067811865475f));
        mu += gv[h];
    }
    mu *= 0.125f;
    float var = 0.f;
    #pragma unroll
    for (int h = 0; h < 8; h++) { float d = gv[h] - mu; var += d * d; }
    var *= 0.125f;
    float rstd = rsqrtf(var + 1e-5f);

    size_t r = (size_t)bid * 256 + tid;
    size_t base = (r >> 9) * 4096 + (r & 511);
    #pragma unroll
    for (int h = 0; h < 8; h++)
        g_rel[base + (size_t)h * 512] = (gv[h] - mu) * rstd * par[8 + h] + par[16 + h];
}

// ===========================================================================
// attn2 v3 (round-11 proven): fused (qk+rel)->softmax->PV; bh offset param.
// ===========================================================================
#define AT_LG 520
#define ATTN2_SMEM_FLOATS (16 * AT_LG + 128 * 36 + 256 * 4 + 16)

__global__ __launch_bounds__(256) void attn2_kernel(int bh0)
{
    extern __shared__ __align__(16) float sm2[];
    float* lg    = sm2;                         // [16][520]
    float* vs    = sm2 + 16 * AT_LG;            // [128][36] chunk
    float* red   = vs + 128 * 36;               // [256][4]
    float* inv_s = red + 256 * 4;               // [16]
    int tid = threadIdx.x;
    int lt = blockIdx.x, bh = bh0 + blockIdx.y;
    int b = bh >> 3, h = bh & 7;

    const float* vb = g_v + (size_t)bh * (512 * 32);

    // logits = (qk + rel) * scale
    size_t base = ((size_t)(b * 512) + lt * 16) * 4096 + (size_t)h * 512;
    #pragma unroll
    for (int j = 0; j < 8; j++) {
        int idx = tid + j * 256;
        int row = idx >> 7, col4 = idx & 127;
        size_t g = base + (size_t)row * 4096 + col4 * 4;
        float4 a = *(const float4*)&g_qk[g];
        float4 c = *(const float4*)&g_rel[g];
        float4 o;
        o.x = (a.x + c.x) * SCALE_; o.y = (a.y + c.y) * SCALE_;
        o.z = (a.z + c.z) * SCALE_; o.w = (a.w + c.w) * SCALE_;
        *(float4*)&lg[row * AT_LG + col4 * 4] = o;
    }
    __syncthreads();

    // softmax: warp w handles rows 2w, 2w+1
    {
        int lane = tid & 31, w = tid >> 5;
        #pragma unroll
        for (int rr = 0; rr < 2; rr++) {
            float* row = &lg[(w * 2 + rr) * AT_LG];
            float vals[16];
            float mx = -1e30f;
            #pragma unroll
            for (int j = 0; j < 16; j++) { vals[j] = row[lane + 32 * j]; mx = fmaxf(mx, vals[j]); }
            #pragma unroll
            for (int o = 16; o > 0; o >>= 1) mx = fmaxf(mx, __shfl_xor_sync(0xffffffff, mx, o));
            float sum = 0.f;
            #pragma unroll
            for (int j = 0; j < 16; j++) {
                float e = __expf(vals[j] - mx);
                row[lane + 32 * j] = e;
                sum += e;
            }
            #pragma unroll
            for (int o = 16; o > 0; o >>= 1) sum += __shfl_xor_sync(0xffffffff, sum, o);
            if (lane == 0) inv_s[w * 2 + rr] = 1.f / sum;
        }
    }
    __syncthreads();

    // PV: thread = (ms = tid>>7, lp = (tid>>4)&7, dp = tid&15)
    int dp = tid & 15, lp = (tid >> 4) & 7, ms = tid >> 7;
    const float* lrow0 = &lg[(lp * 2 + 0) * AT_LG];
    const float* lrow1 = &lg[(lp * 2 + 1) * AT_LG];
    ull acc0 = 0ull, acc1 = 0ull;
    for (int mc = 0; mc < 4; mc++) {
        #pragma unroll
        for (int i = 0; i < 4; i++) {
            int idx = tid + i * 256;
            int r = idx >> 3, c4 = idx & 7;
            *(float4*)&vs[r * 36 + c4 * 4] =
                *(const float4*)&vb[(size_t)(mc * 128 + r) * 32 + c4 * 4];
        }
        __syncthreads();
        int mb = ms * 64;
        const float* l0 = lrow0 + mc * 128 + mb;
        const float* l1 = lrow1 + mc * 128 + mb;
        #pragma unroll 4
        for (int m4 = 0; m4 < 16; m4++) {
            float4 p0 = *(const float4*)&l0[m4 * 4];
            float4 p1 = *(const float4*)&l1[m4 * 4];
            float a0[4] = {p0.x, p0.y, p0.z, p0.w};
            float a1[4] = {p1.x, p1.y, p1.z, p1.w};
            #pragma unroll
            for (int s = 0; s < 4; s++) {
                ull vv = *(const ull*)&vs[(mb + m4 * 4 + s) * 36 + dp * 2];
                ffma2(acc0, pack2(a0[s], a0[s]), vv);
                ffma2(acc1, pack2(a1[s], a1[s]), vv);
            }
        }
        __syncthreads();
    }

    // reduce over m-halves
    {
        float x0, x1, y0, y1;
        unpack2(acc0, x0, x1);
        unpack2(acc1, y0, y1);
        *(float4*)&red[tid * 4] = make_float4(x0, x1, y0, y1);
    }
    __syncthreads();
    {
        int l = tid >> 4, dpo = tid & 15;
        int lpo = l >> 1, io = l & 1;
        int s0 = lpo * 16 + dpo;
        int s1 = 128 + s0;
        float2 v0 = *(const float2*)&red[s0 * 4 + io * 2];
        float2 v1 = *(const float2*)&red[s1 * 4 + io * 2];
        float inv = inv_s[l];
        float2 o = make_float2((v0.x + v1.x) * inv, (v0.y + v1.y) * inv);
        *(float2*)&g_att[((size_t)(b * 512) + lt * 16 + l) * 256 + h * 32 + dpo * 2] = o;
    }
}

// ===========================================================================
extern "C" void kernel_launch(void* const* d_in, const int* in_sizes, int n_in,
                              void* d_out, int out_size)
{
    const float* x      = (const float*)d_in[0];
    const float* rp     = (const float*)d_in[1];
    const float* w_qkv  = (const float*)d_in[2];
    const float* w_rel  = (const float*)d_in[3];
    const float* b_rel  = (const float*)d_in[4];
    const float* ln_g   = (const float*)d_in[5];
    const float* ln_b   = (const float*)d_in[6];
    const float* w_proj = (const float*)d_in[7];
    const float* b_proj = (const float*)d_in[8];
    float* out = (float*)d_out;

    static bool s_init = false;
    static cudaStream_t s_sB;
    static cudaEvent_t s_evF, s_evQK, s_evR0, s_evSide;
    if (!s_init) {
        cudaStreamCreateWithFlags(&s_sB, cudaStreamNonBlocking);
        cudaEventCreateWithFlags(&s_evF,    cudaEventDisableTiming);
        cudaEventCreateWithFlags(&s_evQK,   cudaEventDisableTiming);
        cudaEventCreateWithFlags(&s_evR0,   cudaEventDisableTiming);
        cudaEventCreateWithFlags(&s_evSide, cudaEventDisableTiming);
        cudaFuncSetAttribute(attn2_kernel, cudaFuncAttributeMaxDynamicSharedMemorySize,
                             ATTN2_SMEM_FLOATS * (int)sizeof(float));
        s_init = true;
    }
    int attn2_smem = ATTN2_SMEM_FLOATS * (int)sizeof(float);

    // fork: side stream = qkv gemm + qk
    cudaEventRecord(s_evF, 0);
    cudaStreamWaitEvent(s_sB, s_evF, 0);
    gemm_kernel<<<dim3(16, 24), 128, 0, s_sB>>>(x, w_qkv);
    qk_kernel<<<dim3(16, 16, 2), 256, 0, s_sB>>>();
    cudaEventRecord(s_evQK, s_sB);

    // main stream: rel halves (b=0 then b=1)
    rel_kernel<<<1024, 256>>>(rp, w_rel, b_rel, ln_g, ln_b, 0);
    cudaEventRecord(s_evR0, 0);
    rel_kernel<<<1024, 256>>>(rp, w_rel, b_rel, ln_g, ln_b, 1024);

    // side stream: half-0 tail (b=0) overlapped with rel half-1
    cudaStreamWaitEvent(s_sB, s_evR0, 0);
    attn2_kernel<<<dim3(32, 8), 256, attn2_smem, s_sB>>>(0);
    gemm_proj<<<dim3(16, 8), 256, 0, s_sB>>>(w_proj, b_proj, out, 0);
    cudaEventRecord(s_evSide, s_sB);

    // main stream: half-1 tail (b=1), then join side
    cudaStreamWaitEvent(0, s_evQK, 0);
    attn2_kernel<<<dim3(32, 8), 256, attn2_smem>>>(8);
    gemm_proj<<<dim3(16, 8), 256>>>(w_proj, b_proj, out, 16);
    cudaStreamWaitEvent(0, s_evSide, 0);
}